// round 1
// baseline (speedup 1.0000x reference)
#include <cuda_runtime.h>

#define NN 8192
#define EE 262144
#define SS 4

// Scratch (static __device__ — no allocation allowed)
__device__ __align__(16) float g_Z1[NN * 128];   // layer1: feat @ [W1_b0 | W1_b1]
__device__ __align__(16) float g_ACC1[NN * 64];  // layer1 aggregated (pre-tanh)
__device__ __align__(16) float g_Z2[NN * 64];    // layer2: tanh(ACC1) @ [W2_b0 | W2_b1]
__device__ __align__(16) float g_ACC2[NN * 32];  // layer2 aggregated (pre-tanh)

// ---------------------------------------------------------------------------
// Zero the accumulators (atomics accumulate into them each launch)
// ---------------------------------------------------------------------------
__global__ void zero_kernel() {
    int i = blockIdx.x * blockDim.x + threadIdx.x;
    if (i < NN * 64) g_ACC1[i] = 0.0f;
    if (i < NN * 32) g_ACC2[i] = 0.0f;
}

// ---------------------------------------------------------------------------
// GEMM1: Z1[N,128] = features[N,N] @ Wcat[N,128]
//   Wcat[k, j] = W1[j>>6, k, j&63]   (B=2 bases concatenated along columns)
// Tiling: BM=64, BN=128, BK=32, 256 threads, 4x8 register tile per thread.
// Grid = 128 blocks (one wave-ish on 148 SMs), A read exactly once from DRAM.
// ---------------------------------------------------------------------------
__global__ __launch_bounds__(256) void gemm1_kernel(const float* __restrict__ A,
                                                    const float* __restrict__ W1) {
    __shared__ float As[32][68];   // [k][m], padded (68 % 4 == 0 for float4 rows)
    __shared__ float Bs[32][128];  // [k][n]

    const int tid = threadIdx.x;
    const int tx = tid & 15;       // 0..15 -> 8 output cols each
    const int ty = tid >> 4;       // 0..15 -> 4 output rows each
    const int row0 = blockIdx.x * 64;

    float acc[4][8];
#pragma unroll
    for (int i = 0; i < 4; i++)
#pragma unroll
        for (int j = 0; j < 8; j++) acc[i][j] = 0.0f;

    for (int k0 = 0; k0 < NN; k0 += 32) {
        // Load A tile: 64 rows x 32 k (512 float4, 2 per thread), store transposed
#pragma unroll
        for (int i = 0; i < 2; i++) {
            int idx = tid + i * 256;          // 0..511
            int r  = idx >> 3;                // 0..63
            int k4 = (idx & 7) << 2;          // 0,4,...,28
            float4 v = *(const float4*)(A + (size_t)(row0 + r) * NN + k0 + k4);
            As[k4 + 0][r] = v.x;
            As[k4 + 1][r] = v.y;
            As[k4 + 2][r] = v.z;
            As[k4 + 3][r] = v.w;
        }
        // Load B tile: 32 k x 128 cols (1024 float4, 4 per thread)
#pragma unroll
        for (int i = 0; i < 4; i++) {
            int idx = tid + i * 256;          // 0..1023
            int kk  = idx >> 5;               // 0..31
            int col = (idx & 31) << 2;        // 0..124
            int b = col >> 6;
            int h = col & 63;
            *(float4*)&Bs[kk][col] =
                *(const float4*)(W1 + (size_t)b * NN * 64 + (size_t)(k0 + kk) * 64 + h);
        }
        __syncthreads();

#pragma unroll
        for (int k = 0; k < 32; k++) {
            float4 a4 = *(const float4*)&As[k][ty << 2];
            float4 b0 = *(const float4*)&Bs[k][tx << 3];
            float4 b1 = *(const float4*)&Bs[k][(tx << 3) + 4];
            float av[4] = {a4.x, a4.y, a4.z, a4.w};
            float bv[8] = {b0.x, b0.y, b0.z, b0.w, b1.x, b1.y, b1.z, b1.w};
#pragma unroll
            for (int i = 0; i < 4; i++)
#pragma unroll
                for (int j = 0; j < 8; j++)
                    acc[i][j] = fmaf(av[i], bv[j], acc[i][j]);
        }
        __syncthreads();
    }

#pragma unroll
    for (int i = 0; i < 4; i++) {
        int r = row0 + (ty << 2) + i;
        float4 o0 = make_float4(acc[i][0], acc[i][1], acc[i][2], acc[i][3]);
        float4 o1 = make_float4(acc[i][4], acc[i][5], acc[i][6], acc[i][7]);
        *(float4*)&g_Z1[(size_t)r * 128 + (tx << 3)]     = o0;
        *(float4*)&g_Z1[(size_t)r * 128 + (tx << 3) + 4] = o1;
    }
}

// ---------------------------------------------------------------------------
// Aggregation layer 1: for every edge e of relation s:
//   ACC1[dst, h] += w_e * (Wc1[s,0]*Z1[src,h] + Wc1[s,1]*Z1[src,64+h])
// One thread per (edge, 4-col group); 16 groups cover H=64. red.v4 atomics.
// Total threads = S*E*16 = 16,777,216 (exact grid, no bounds check needed).
// ---------------------------------------------------------------------------
__global__ __launch_bounds__(256) void agg1_kernel(const int* __restrict__ src,
                                                   const int* __restrict__ dst,
                                                   const float* __restrict__ w,
                                                   const float* __restrict__ Wc) {
    int idx = blockIdx.x * blockDim.x + threadIdx.x;
    int e = idx >> 4;               // global edge id over S*E
    int g = (idx & 15) << 2;        // column group (0,4,...,60)
    int s = e >> 18;                // E = 2^18
    float c0 = Wc[2 * s];
    float c1 = Wc[2 * s + 1];
    int   sn = src[e];
    int   dn = dst[e];
    float we = w[e];

    float4 z0 = *(const float4*)&g_Z1[(size_t)sn * 128 + g];
    float4 z1 = *(const float4*)&g_Z1[(size_t)sn * 128 + 64 + g];
    float4 m;
    m.x = we * fmaf(c0, z0.x, c1 * z1.x);
    m.y = we * fmaf(c0, z0.y, c1 * z1.y);
    m.z = we * fmaf(c0, z0.z, c1 * z1.z);
    m.w = we * fmaf(c0, z0.w, c1 * z1.w);

    float* p = &g_ACC1[(size_t)dn * 64 + g];
    asm volatile("red.global.add.v4.f32 [%0], {%1, %2, %3, %4};"
                 :: "l"(p), "f"(m.x), "f"(m.y), "f"(m.z), "f"(m.w) : "memory");
}

// ---------------------------------------------------------------------------
// GEMM2: Z2[N,64] = tanh(ACC1)[N,64] @ W2cat[64,64]
//   W2cat[k, j] = W2[j>>5, k, j&31]    (tanh fused into the A-tile load)
// 64 rows per block, full K=64 and all 64 cols in shared memory.
// ---------------------------------------------------------------------------
__global__ __launch_bounds__(256) void gemm2_kernel(const float* __restrict__ W2) {
    __shared__ float As[64][68];   // padded
    __shared__ float Bs[64][64];

    const int tid = threadIdx.x;
    const int tx = tid & 15;       // 4 cols each
    const int ty = tid >> 4;       // rows ty, ty+16, ty+32, ty+48
    const int row0 = blockIdx.x * 64;

#pragma unroll
    for (int i = 0; i < 4; i++) {
        int idx = tid + i * 256;      // 1024 float4
        int r = idx >> 4;
        int c = (idx & 15) << 2;
        float4 v = *(const float4*)&g_ACC1[(size_t)(row0 + r) * 64 + c];
        v.x = tanhf(v.x); v.y = tanhf(v.y); v.z = tanhf(v.z); v.w = tanhf(v.w);
        *(float4*)&As[r][c] = v;
    }
#pragma unroll
    for (int i = 0; i < 4; i++) {
        int idx = tid + i * 256;
        int k   = idx >> 4;
        int col = (idx & 15) << 2;
        int b = col >> 5;
        int h = col & 31;
        *(float4*)&Bs[k][col] = *(const float4*)(W2 + (size_t)b * 64 * 32 + (size_t)k * 32 + h);
    }
    __syncthreads();

    float acc[4][4];
#pragma unroll
    for (int i = 0; i < 4; i++)
#pragma unroll
        for (int j = 0; j < 4; j++) acc[i][j] = 0.0f;

#pragma unroll
    for (int k = 0; k < 64; k++) {
        float4 b4 = *(const float4*)&Bs[k][tx << 2];
        float bv[4] = {b4.x, b4.y, b4.z, b4.w};
#pragma unroll
        for (int i = 0; i < 4; i++) {
            float a = As[ty + i * 16][k];
#pragma unroll
            for (int j = 0; j < 4; j++)
                acc[i][j] = fmaf(a, bv[j], acc[i][j]);
        }
    }

#pragma unroll
    for (int i = 0; i < 4; i++) {
        int r = row0 + ty + i * 16;
        float4 o = make_float4(acc[i][0], acc[i][1], acc[i][2], acc[i][3]);
        *(float4*)&g_Z2[(size_t)r * 64 + (tx << 2)] = o;
    }
}

// ---------------------------------------------------------------------------
// Aggregation layer 2: F=32 cols -> 8 groups of 4 per edge. S*E*8 = 8,388,608.
// ---------------------------------------------------------------------------
__global__ __launch_bounds__(256) void agg2_kernel(const int* __restrict__ src,
                                                   const int* __restrict__ dst,
                                                   const float* __restrict__ w,
                                                   const float* __restrict__ Wc) {
    int idx = blockIdx.x * blockDim.x + threadIdx.x;
    int e = idx >> 3;
    int g = (idx & 7) << 2;
    int s = e >> 18;
    float c0 = Wc[2 * s];
    float c1 = Wc[2 * s + 1];
    int   sn = src[e];
    int   dn = dst[e];
    float we = w[e];

    float4 z0 = *(const float4*)&g_Z2[(size_t)sn * 64 + g];
    float4 z1 = *(const float4*)&g_Z2[(size_t)sn * 64 + 32 + g];
    float4 m;
    m.x = we * fmaf(c0, z0.x, c1 * z1.x);
    m.y = we * fmaf(c0, z0.y, c1 * z1.y);
    m.z = we * fmaf(c0, z0.z, c1 * z1.z);
    m.w = we * fmaf(c0, z0.w, c1 * z1.w);

    float* p = &g_ACC2[(size_t)dn * 32 + g];
    asm volatile("red.global.add.v4.f32 [%0], {%1, %2, %3, %4};"
                 :: "l"(p), "f"(m.x), "f"(m.y), "f"(m.z), "f"(m.w) : "memory");
}

// ---------------------------------------------------------------------------
// Classifier: out[n, c] = tanh(ACC2[n,:]) @ Wclf + bclf      (C = 2)
// ---------------------------------------------------------------------------
__global__ void final_kernel(const float* __restrict__ Wclf,
                             const float* __restrict__ bclf,
                             float* __restrict__ out) {
    int n = blockIdx.x * blockDim.x + threadIdx.x;
    if (n >= NN) return;
    float a0 = bclf[0];
    float a1 = bclf[1];
#pragma unroll
    for (int f = 0; f < 32; f++) {
        float v = tanhf(g_ACC2[(size_t)n * 32 + f]);
        a0 = fmaf(v, Wclf[2 * f],     a0);
        a1 = fmaf(v, Wclf[2 * f + 1], a1);
    }
    out[2 * n]     = a0;
    out[2 * n + 1] = a1;
}

// ---------------------------------------------------------------------------
extern "C" void kernel_launch(void* const* d_in, const int* in_sizes, int n_in,
                              void* d_out, int out_size) {
    const float* features = (const float*)d_in[0];  // [N, N]
    const float* edge_w   = (const float*)d_in[1];  // [S, E]
    const float* W1       = (const float*)d_in[2];  // [B, N, H]
    const float* Wc1      = (const float*)d_in[3];  // [S, B]
    const float* W2       = (const float*)d_in[4];  // [B, H, F]
    const float* Wc2      = (const float*)d_in[5];  // [S, B]
    const float* Wclf     = (const float*)d_in[6];  // [F, C]
    const float* bclf     = (const float*)d_in[7];  // [C]
    const int*   edge_src = (const int*)d_in[8];    // [S, E]
    const int*   edge_dst = (const int*)d_in[9];    // [S, E]
    float* out = (float*)d_out;                      // [N, C]

    zero_kernel<<<(NN * 64 + 255) / 256, 256>>>();
    gemm1_kernel<<<NN / 64, 256>>>(features, W1);
    agg1_kernel<<<(SS * EE * 16) / 256, 256>>>(edge_src, edge_dst, edge_w, Wc1);
    gemm2_kernel<<<NN / 64, 256>>>(W2);
    agg2_kernel<<<(SS * EE * 8) / 256, 256>>>(edge_src, edge_dst, edge_w, Wc2);
    final_kernel<<<(NN + 255) / 256, 256>>>(Wclf, bclf, out);
}

// round 3
// speedup vs baseline: 2.1912x; 2.1912x over previous
#include <cuda_runtime.h>
#include <cuda_bf16.h>
#include <cstdint>

#define NN 8192
#define EE 262144
#define SS 4

// ---------------------------------------------------------------------------
// Scratch (static __device__ — no allocation allowed)
// ---------------------------------------------------------------------------
__device__ __align__(16) float g_Z1[NN * 128];   // layer1: feat @ [W1_b0 | W1_b1]
__device__ __align__(16) float g_ACC1[NN * 64];  // layer1 aggregated (pre-tanh)
__device__ __align__(16) float g_Z2[NN * 64];    // layer2: tanh(ACC1) @ [W2_b0 | W2_b1]
__device__ __align__(16) float g_ACC2[NN * 32];  // layer2 aggregated (pre-tanh)
// bf16 hi/lo split of Wcat, layout [n (0..127)][k (0..8191)]  (K-major rows)
__device__ __align__(16) __nv_bfloat16 g_Bhi[128 * NN];
__device__ __align__(16) __nv_bfloat16 g_Blo[128 * NN];

__device__ __forceinline__ uint32_t smem_u32(const void* p) {
    uint32_t a;
    asm("{ .reg .u64 t; cvta.to.shared.u64 t, %1; cvt.u32.u64 %0, t; }" : "=r"(a) : "l"(p));
    return a;
}

__device__ __forceinline__ void ldsm_x4(uint32_t* r, uint32_t addr) {
    asm volatile("ldmatrix.sync.aligned.m8n8.x4.shared.b16 {%0,%1,%2,%3}, [%4];"
                 : "=r"(r[0]), "=r"(r[1]), "=r"(r[2]), "=r"(r[3]) : "r"(addr));
}

__device__ __forceinline__ void mma_bf16(float* d, const uint32_t* a,
                                         uint32_t b0, uint32_t b1) {
    asm volatile(
        "mma.sync.aligned.m16n8k16.row.col.f32.bf16.bf16.f32 "
        "{%0,%1,%2,%3}, {%4,%5,%6,%7}, {%8,%9}, {%0,%1,%2,%3};"
        : "+f"(d[0]), "+f"(d[1]), "+f"(d[2]), "+f"(d[3])
        : "r"(a[0]), "r"(a[1]), "r"(a[2]), "r"(a[3]), "r"(b0), "r"(b1));
}

__device__ __forceinline__ void split_bf16(float v, uint16_t& h, uint16_t& l) {
    __nv_bfloat16 bh = __float2bfloat16(v);
    h = __bfloat16_as_ushort(bh);
    l = __bfloat16_as_ushort(__float2bfloat16(v - __bfloat162float(bh)));
}

// ---------------------------------------------------------------------------
// Zero accumulators (atomics accumulate into them each launch)
// ---------------------------------------------------------------------------
__global__ void zero_kernel() {
    int i = blockIdx.x * blockDim.x + threadIdx.x;
    if (i < NN * 64) g_ACC1[i] = 0.0f;
    if (i < NN * 32) g_ACC2[i] = 0.0f;
}

// ---------------------------------------------------------------------------
// Prep: Wcat -> bf16 hi/lo in [n][k] K-major layout
//   Wcat[k, n] = W1[n>>6, k, n&63]
// ---------------------------------------------------------------------------
__global__ __launch_bounds__(256) void prep_b_kernel(const float* __restrict__ W1) {
    int k0 = blockIdx.x * 64;
    int tid = threadIdx.x;
#pragma unroll 8
    for (int i = 0; i < 32; i++) {
        int idx = tid + i * 256;      // 0..8191
        int n = idx >> 6;             // 0..127
        int k = idx & 63;
        float x = W1[(size_t)(n >> 6) * NN * 64 + (size_t)(k0 + k) * 64 + (n & 63)];
        uint16_t h, l;
        split_bf16(x, h, l);
        g_Bhi[(size_t)n * NN + k0 + k] = __ushort_as_bfloat16(h);
        g_Blo[(size_t)n * NN + k0 + k] = __ushort_as_bfloat16(l);
    }
}

// ---------------------------------------------------------------------------
// GEMM1 via mma.sync bf16 (3-term hi/lo compensation, fp32 accum):
//   Z1[8192,128] = features @ Wcat
// BM=64, BN=128, BK=32. 8 warps as 2(M) x 4(N), warp tile 32x32.
// smem rows padded to 40 bf16 (80B) -> conflict-free ldmatrix.
// Double-buffered smem + register prefetch, 1 syncthreads/iter.
// ---------------------------------------------------------------------------
#define AH_OFF 0
#define AL_OFF 5120                 // 64*40*2
#define BH_OFF 10240
#define BL_OFF 20480                // BH + 128*40*2
#define STAGE_BYTES 30720
#define GEMM1_SMEM (2 * STAGE_BYTES)

__global__ __launch_bounds__(256, 1) void gemm1_mma(const float* __restrict__ A) {
    extern __shared__ char sm[];
    const int tid = threadIdx.x;
    const int lane = tid & 31;
    const int wid = tid >> 5;
    const int row0 = blockIdx.x * 64;
    const int wm = wid & 1;          // 0..1 -> 32 rows
    const int wn = wid >> 1;         // 0..3 -> 32 cols
    const uint32_t sb = smem_u32(sm);

    // global-load assignments
    const int ar = tid >> 2;                 // 0..63   A row in tile
    const int ak = (tid & 3) << 3;           // 0,8,16,24
    const int br = tid >> 1;                 // 0..127  B n-row
    const int bk = (tid & 1) << 4;           // 0,16
    const float* Abase = A + (size_t)(row0 + ar) * NN + ak;
    const __nv_bfloat16* BhB = g_Bhi + (size_t)br * NN + bk;
    const __nv_bfloat16* BlB = g_Blo + (size_t)br * NN + bk;

    // per-thread smem byte offsets for stores
    const uint32_t stA = (uint32_t)(ar * 80 + ak * 2);
    const uint32_t stB = (uint32_t)(br * 80 + bk * 2);

    // ldmatrix offsets (within a stage)
    const int frow = lane & 15;
    const int fkg = (lane >> 4) << 3;        // 0 or 8
    const uint32_t lmA = (uint32_t)((wm * 32 + frow) * 80 + fkg * 2);
    const uint32_t lmB = (uint32_t)((wn * 32 + frow) * 80 + fkg * 2);

    float acc[2][4][4];
#pragma unroll
    for (int i = 0; i < 2; i++)
#pragma unroll
        for (int j = 0; j < 4; j++)
#pragma unroll
            for (int q = 0; q < 4; q++) acc[i][j][q] = 0.0f;

    float4 apf0, apf1, bh0, bh1, bl0, bl1;

    auto loadG = [&](int kt) {
        apf0 = *(const float4*)(Abase + kt);
        apf1 = *(const float4*)(Abase + kt + 4);
        bh0 = *(const float4*)(BhB + kt);
        bh1 = *(const float4*)(BhB + kt + 8);
        bl0 = *(const float4*)(BlB + kt);
        bl1 = *(const float4*)(BlB + kt + 8);
    };

    auto storeStage = [&](int s) {
        char* st = sm + s * STAGE_BYTES;
        float vs[8] = {apf0.x, apf0.y, apf0.z, apf0.w, apf1.x, apf1.y, apf1.z, apf1.w};
        uint32_t hw[4], lw[4];
#pragma unroll
        for (int i = 0; i < 4; i++) {
            uint16_t h0, l0, h1, l1;
            split_bf16(vs[2 * i], h0, l0);
            split_bf16(vs[2 * i + 1], h1, l1);
            hw[i] = ((uint32_t)h1 << 16) | h0;
            lw[i] = ((uint32_t)l1 << 16) | l0;
        }
        *(uint4*)(st + AH_OFF + stA) = make_uint4(hw[0], hw[1], hw[2], hw[3]);
        *(uint4*)(st + AL_OFF + stA) = make_uint4(lw[0], lw[1], lw[2], lw[3]);
        *(float4*)(st + BH_OFF + stB)      = bh0;
        *(float4*)(st + BH_OFF + stB + 16) = bh1;
        *(float4*)(st + BL_OFF + stB)      = bl0;
        *(float4*)(st + BL_OFF + stB + 16) = bl1;
    };

    auto compute = [&](int s) {
        uint32_t stb = sb + s * STAGE_BYTES;
#pragma unroll
        for (int ks = 0; ks < 2; ks++) {
            uint32_t ko = (uint32_t)(ks * 32);   // 16 elems * 2B
            uint32_t ah[2][4], al[2][4], bhf[2][4], blf[2][4];
            ldsm_x4(ah[0], stb + AH_OFF + lmA + ko);
            ldsm_x4(ah[1], stb + AH_OFF + lmA + ko + 16 * 80);
            ldsm_x4(al[0], stb + AL_OFF + lmA + ko);
            ldsm_x4(al[1], stb + AL_OFF + lmA + ko + 16 * 80);
            ldsm_x4(bhf[0], stb + BH_OFF + lmB + ko);
            ldsm_x4(bhf[1], stb + BH_OFF + lmB + ko + 16 * 80);
            ldsm_x4(blf[0], stb + BL_OFF + lmB + ko);
            ldsm_x4(blf[1], stb + BL_OFF + lmB + ko + 16 * 80);
#pragma unroll
            for (int mt = 0; mt < 2; mt++) {
#pragma unroll
                for (int nb = 0; nb < 2; nb++) {
#pragma unroll
                    for (int nt = 0; nt < 2; nt++) {
                        float* d = acc[mt][nb * 2 + nt];
                        mma_bf16(d, ah[mt], bhf[nb][nt], bhf[nb][nt + 2]); // hi*hi
                        mma_bf16(d, ah[mt], blf[nb][nt], blf[nb][nt + 2]); // hi*lo
                        mma_bf16(d, al[mt], bhf[nb][nt], bhf[nb][nt + 2]); // lo*hi
                    }
                }
            }
        }
    };

    const int NT = NN / 32;   // 256
    loadG(0);
    storeStage(0);
    __syncthreads();

    for (int t = 0; t < NT; t++) {
        int s = t & 1;
        if (t + 1 < NT) loadG((t + 1) * 32);
        compute(s);
        if (t + 1 < NT) storeStage(s ^ 1);
        __syncthreads();
    }

    // Epilogue: direct fp32 stores
#pragma unroll
    for (int mt = 0; mt < 2; mt++) {
#pragma unroll
        for (int j = 0; j < 4; j++) {
            int m = row0 + wm * 32 + mt * 16 + (lane >> 2);
            int n = wn * 32 + j * 8 + (lane & 3) * 2;
            *(float2*)&g_Z1[(size_t)m * 128 + n] =
                make_float2(acc[mt][j][0], acc[mt][j][1]);
            *(float2*)&g_Z1[(size_t)(m + 8) * 128 + n] =
                make_float2(acc[mt][j][2], acc[mt][j][3]);
        }
    }
}

// ---------------------------------------------------------------------------
// Aggregation layer 1: red.v4 atomics over S*E*16 threads
// ---------------------------------------------------------------------------
__global__ __launch_bounds__(256) void agg1_kernel(const int* __restrict__ src,
                                                   const int* __restrict__ dst,
                                                   const float* __restrict__ w,
                                                   const float* __restrict__ Wc) {
    int idx = blockIdx.x * blockDim.x + threadIdx.x;
    int e = idx >> 4;
    int g = (idx & 15) << 2;
    int s = e >> 18;
    float c0 = Wc[2 * s];
    float c1 = Wc[2 * s + 1];
    int   sn = src[e];
    int   dn = dst[e];
    float we = w[e];

    float4 z0 = *(const float4*)&g_Z1[(size_t)sn * 128 + g];
    float4 z1 = *(const float4*)&g_Z1[(size_t)sn * 128 + 64 + g];
    float4 m;
    m.x = we * fmaf(c0, z0.x, c1 * z1.x);
    m.y = we * fmaf(c0, z0.y, c1 * z1.y);
    m.z = we * fmaf(c0, z0.z, c1 * z1.z);
    m.w = we * fmaf(c0, z0.w, c1 * z1.w);

    float* p = &g_ACC1[(size_t)dn * 64 + g];
    asm volatile("red.global.add.v4.f32 [%0], {%1, %2, %3, %4};"
                 :: "l"(p), "f"(m.x), "f"(m.y), "f"(m.z), "f"(m.w) : "memory");
}

// ---------------------------------------------------------------------------
// GEMM2: Z2 = tanh(ACC1) @ W2cat
// ---------------------------------------------------------------------------
__global__ __launch_bounds__(256) void gemm2_kernel(const float* __restrict__ W2) {
    __shared__ float As[64][68];
    __shared__ float Bs[64][64];

    const int tid = threadIdx.x;
    const int tx = tid & 15;
    const int ty = tid >> 4;
    const int row0 = blockIdx.x * 64;

#pragma unroll
    for (int i = 0; i < 4; i++) {
        int idx = tid + i * 256;
        int r = idx >> 4;
        int c = (idx & 15) << 2;
        float4 v = *(const float4*)&g_ACC1[(size_t)(row0 + r) * 64 + c];
        v.x = tanhf(v.x); v.y = tanhf(v.y); v.z = tanhf(v.z); v.w = tanhf(v.w);
        *(float4*)&As[r][c] = v;
    }
#pragma unroll
    for (int i = 0; i < 4; i++) {
        int idx = tid + i * 256;
        int k   = idx >> 4;
        int col = (idx & 15) << 2;
        int b = col >> 5;
        int h = col & 31;
        *(float4*)&Bs[k][col] = *(const float4*)(W2 + (size_t)b * 64 * 32 + (size_t)k * 32 + h);
    }
    __syncthreads();

    float acc[4][4];
#pragma unroll
    for (int i = 0; i < 4; i++)
#pragma unroll
        for (int j = 0; j < 4; j++) acc[i][j] = 0.0f;

#pragma unroll
    for (int k = 0; k < 64; k++) {
        float4 b4 = *(const float4*)&Bs[k][tx << 2];
        float bv[4] = {b4.x, b4.y, b4.z, b4.w};
#pragma unroll
        for (int i = 0; i < 4; i++) {
            float a = As[ty + i * 16][k];
#pragma unroll
            for (int j = 0; j < 4; j++)
                acc[i][j] = fmaf(a, bv[j], acc[i][j]);
        }
    }

#pragma unroll
    for (int i = 0; i < 4; i++) {
        int r = row0 + ty + i * 16;
        float4 o = make_float4(acc[i][0], acc[i][1], acc[i][2], acc[i][3]);
        *(float4*)&g_Z2[(size_t)r * 64 + (tx << 2)] = o;
    }
}

// ---------------------------------------------------------------------------
// Aggregation layer 2
// ---------------------------------------------------------------------------
__global__ __launch_bounds__(256) void agg2_kernel(const int* __restrict__ src,
                                                   const int* __restrict__ dst,
                                                   const float* __restrict__ w,
                                                   const float* __restrict__ Wc) {
    int idx = blockIdx.x * blockDim.x + threadIdx.x;
    int e = idx >> 3;
    int g = (idx & 7) << 2;
    int s = e >> 18;
    float c0 = Wc[2 * s];
    float c1 = Wc[2 * s + 1];
    int   sn = src[e];
    int   dn = dst[e];
    float we = w[e];

    float4 z0 = *(const float4*)&g_Z2[(size_t)sn * 64 + g];
    float4 z1 = *(const float4*)&g_Z2[(size_t)sn * 64 + 32 + g];
    float4 m;
    m.x = we * fmaf(c0, z0.x, c1 * z1.x);
    m.y = we * fmaf(c0, z0.y, c1 * z1.y);
    m.z = we * fmaf(c0, z0.z, c1 * z1.z);
    m.w = we * fmaf(c0, z0.w, c1 * z1.w);

    float* p = &g_ACC2[(size_t)dn * 32 + g];
    asm volatile("red.global.add.v4.f32 [%0], {%1, %2, %3, %4};"
                 :: "l"(p), "f"(m.x), "f"(m.y), "f"(m.z), "f"(m.w) : "memory");
}

// ---------------------------------------------------------------------------
// Classifier
// ---------------------------------------------------------------------------
__global__ void final_kernel(const float* __restrict__ Wclf,
                             const float* __restrict__ bclf,
                             float* __restrict__ out) {
    int n = blockIdx.x * blockDim.x + threadIdx.x;
    if (n >= NN) return;
    float a0 = bclf[0];
    float a1 = bclf[1];
#pragma unroll
    for (int f = 0; f < 32; f++) {
        float v = tanhf(g_ACC2[(size_t)n * 32 + f]);
        a0 = fmaf(v, Wclf[2 * f],     a0);
        a1 = fmaf(v, Wclf[2 * f + 1], a1);
    }
    out[2 * n]     = a0;
    out[2 * n + 1] = a1;
}

// ---------------------------------------------------------------------------
extern "C" void kernel_launch(void* const* d_in, const int* in_sizes, int n_in,
                              void* d_out, int out_size) {
    const float* features = (const float*)d_in[0];
    const float* edge_w   = (const float*)d_in[1];
    const float* W1       = (const float*)d_in[2];
    const float* Wc1      = (const float*)d_in[3];
    const float* W2       = (const float*)d_in[4];
    const float* Wc2      = (const float*)d_in[5];
    const float* Wclf     = (const float*)d_in[6];
    const float* bclf     = (const float*)d_in[7];
    const int*   edge_src = (const int*)d_in[8];
    const int*   edge_dst = (const int*)d_in[9];
    float* out = (float*)d_out;

    static int configured = 0;
    cudaFuncSetAttribute(gemm1_mma, cudaFuncAttributeMaxDynamicSharedMemorySize,
                         GEMM1_SMEM);
    (void)configured;

    zero_kernel<<<(NN * 64 + 255) / 256, 256>>>();
    prep_b_kernel<<<NN / 64, 256>>>(W1);
    gemm1_mma<<<NN / 64, 256, GEMM1_SMEM>>>(features);
    agg1_kernel<<<(SS * EE * 16) / 256, 256>>>(edge_src, edge_dst, edge_w, Wc1);
    gemm2_kernel<<<NN / 64, 256>>>(W2);
    agg2_kernel<<<(SS * EE * 8) / 256, 256>>>(edge_src, edge_dst, edge_w, Wc2);
    final_kernel<<<(NN + 255) / 256, 256>>>(Wclf, bclf, out);
}

// round 5
// speedup vs baseline: 2.5713x; 1.1735x over previous
#include <cuda_runtime.h>
#include <cuda_bf16.h>
#include <cstdint>

#define NN 8192
#define EE 262144
#define SS 4

// ---------------------------------------------------------------------------
// Scratch (static __device__ — no allocation allowed)
// ---------------------------------------------------------------------------
__device__ __align__(16) float g_Z1[NN * 128];    // layer1 GEMM out (split-K accum)
__device__ __align__(16) float g_SUP1[SS * NN * 64]; // per-relation supports L1
__device__ __align__(16) float g_ACC1[NN * 64];   // layer1 aggregated (pre-tanh)
__device__ __align__(16) float g_Z2[NN * 64];     // layer2 GEMM out
__device__ __align__(16) float g_SUP2[SS * NN * 32]; // per-relation supports L2
__device__ __align__(16) float g_ACC2[NN * 32];   // layer2 aggregated (pre-tanh)
// bf16 hi/lo split of Wcat, layout [n (0..127)][k (0..8191)]  (K-major rows)
__device__ __align__(16) __nv_bfloat16 g_Bhi[128 * NN];
__device__ __align__(16) __nv_bfloat16 g_Blo[128 * NN];

__device__ __forceinline__ uint32_t smem_u32(const void* p) {
    uint32_t a;
    asm("{ .reg .u64 t; cvta.to.shared.u64 t, %1; cvt.u32.u64 %0, t; }" : "=r"(a) : "l"(p));
    return a;
}

__device__ __forceinline__ void ldsm_x4(uint32_t* r, uint32_t addr) {
    asm volatile("ldmatrix.sync.aligned.m8n8.x4.shared.b16 {%0,%1,%2,%3}, [%4];"
                 : "=r"(r[0]), "=r"(r[1]), "=r"(r[2]), "=r"(r[3]) : "r"(addr));
}

__device__ __forceinline__ void mma_bf16(float* d, const uint32_t* a,
                                         uint32_t b0, uint32_t b1) {
    asm volatile(
        "mma.sync.aligned.m16n8k16.row.col.f32.bf16.bf16.f32 "
        "{%0,%1,%2,%3}, {%4,%5,%6,%7}, {%8,%9}, {%0,%1,%2,%3};"
        : "+f"(d[0]), "+f"(d[1]), "+f"(d[2]), "+f"(d[3])
        : "r"(a[0]), "r"(a[1]), "r"(a[2]), "r"(a[3]), "r"(b0), "r"(b1));
}

__device__ __forceinline__ void split_bf16(float v, uint16_t& h, uint16_t& l) {
    __nv_bfloat16 bh = __float2bfloat16(v);
    h = __bfloat16_as_ushort(bh);
    l = __bfloat16_as_ushort(__float2bfloat16(v - __bfloat162float(bh)));
}

// ---------------------------------------------------------------------------
// Zero: g_Z1 (split-K target) + both aggregation accumulators
// ---------------------------------------------------------------------------
__global__ void zero_kernel() {
    int i = blockIdx.x * blockDim.x + threadIdx.x;
    if (i < NN * 128) g_Z1[i] = 0.0f;
    if (i < NN * 64) g_ACC1[i] = 0.0f;
    if (i < NN * 32) g_ACC2[i] = 0.0f;
}

// ---------------------------------------------------------------------------
// Prep: Wcat -> bf16 hi/lo in [n][k] K-major layout
// ---------------------------------------------------------------------------
__global__ __launch_bounds__(256) void prep_b_kernel(const float* __restrict__ W1) {
    int k0 = blockIdx.x * 64;
    int tid = threadIdx.x;
#pragma unroll 8
    for (int i = 0; i < 32; i++) {
        int idx = tid + i * 256;      // 0..8191
        int n = idx >> 6;             // 0..127
        int k = idx & 63;
        float x = W1[(size_t)(n >> 6) * NN * 64 + (size_t)(k0 + k) * 64 + (n & 63)];
        uint16_t h, l;
        split_bf16(x, h, l);
        g_Bhi[(size_t)n * NN + k0 + k] = __ushort_as_bfloat16(h);
        g_Blo[(size_t)n * NN + k0 + k] = __ushort_as_bfloat16(l);
    }
}

// ---------------------------------------------------------------------------
// GEMM1: Z1[8192,128] += features[rows, Kslice] @ Wcat
// BM=128, BN=128, BK=32, split-K=2 (grid 64x2 = 128 CTAs).
// 8 warps as 2(M) x 4(N); warp tile 64x32.
// 3-term bf16 compensation (hi*hi + hi*lo + lo*hi), fp32 accum.
// smem rows padded to 40 bf16 (80B); double-buffer + register prefetch.
// ---------------------------------------------------------------------------
#define AH_OFF 0
#define AL_OFF 10240                 // 128*80
#define BH_OFF 20480
#define BL_OFF 30720
#define STAGE_BYTES 40960
#define GEMM1_SMEM (2 * STAGE_BYTES)

__global__ __launch_bounds__(256, 1) void gemm1_mma(const float* __restrict__ A) {
    extern __shared__ char sm[];
    const int tid = threadIdx.x;
    const int lane = tid & 31;
    const int wid = tid >> 5;
    const int row0 = blockIdx.x * 128;
    const int kbeg = blockIdx.y * (NN / 2);
    const int wm = wid & 1;          // 0..1 -> 64-row half
    const int wn = wid >> 1;         // 0..3 -> 32-col quarter
    const uint32_t sb = smem_u32(sm);

    // global-load assignments: thread covers row=tid>>1, k=(tid&1)*16..+15
    const int gr = tid >> 1;                 // 0..127
    const int gk = (tid & 1) << 4;           // 0 or 16
    const float* Abase = A + (size_t)(row0 + gr) * NN + kbeg + gk;
    const __nv_bfloat16* BhB = g_Bhi + (size_t)gr * NN + kbeg + gk;
    const __nv_bfloat16* BlB = g_Blo + (size_t)gr * NN + kbeg + gk;
    const uint32_t stO = (uint32_t)(gr * 80 + gk * 2);   // smem store offset

    // ldmatrix offsets
    const int frow = lane & 15;
    const int fkB = (lane >> 4) << 3;        // 0 or 8 (k elems)
    const uint32_t lmA = (uint32_t)((wm * 64 + frow) * 80 + fkB * 2);
    const uint32_t lmB = (uint32_t)((wn * 32 + frow) * 80 + fkB * 2);

    float acc[4][4][4];
#pragma unroll
    for (int i = 0; i < 4; i++)
#pragma unroll
        for (int j = 0; j < 4; j++)
#pragma unroll
            for (int q = 0; q < 4; q++) acc[i][j][q] = 0.0f;

    float4 a0, a1, a2, a3, bh0, bh1, bl0, bl1;

    auto loadG = [&](int kt) {
        a0 = *(const float4*)(Abase + kt);
        a1 = *(const float4*)(Abase + kt + 4);
        a2 = *(const float4*)(Abase + kt + 8);
        a3 = *(const float4*)(Abase + kt + 12);
        bh0 = *(const float4*)(BhB + kt);
        bh1 = *(const float4*)(BhB + kt + 8);
        bl0 = *(const float4*)(BlB + kt);
        bl1 = *(const float4*)(BlB + kt + 8);
    };

    auto storeStage = [&](int s) {
        char* st = sm + s * STAGE_BYTES;
        float vs[16] = {a0.x, a0.y, a0.z, a0.w, a1.x, a1.y, a1.z, a1.w,
                        a2.x, a2.y, a2.z, a2.w, a3.x, a3.y, a3.z, a3.w};
        uint32_t hw[8], lw[8];
#pragma unroll
        for (int i = 0; i < 8; i++) {
            uint16_t h0, l0, h1, l1;
            split_bf16(vs[2 * i], h0, l0);
            split_bf16(vs[2 * i + 1], h1, l1);
            hw[i] = ((uint32_t)h1 << 16) | h0;
            lw[i] = ((uint32_t)l1 << 16) | l0;
        }
        *(uint4*)(st + AH_OFF + stO)      = make_uint4(hw[0], hw[1], hw[2], hw[3]);
        *(uint4*)(st + AH_OFF + stO + 16) = make_uint4(hw[4], hw[5], hw[6], hw[7]);
        *(uint4*)(st + AL_OFF + stO)      = make_uint4(lw[0], lw[1], lw[2], lw[3]);
        *(uint4*)(st + AL_OFF + stO + 16) = make_uint4(lw[4], lw[5], lw[6], lw[7]);
        *(float4*)(st + BH_OFF + stO)      = bh0;
        *(float4*)(st + BH_OFF + stO + 16) = bh1;
        *(float4*)(st + BL_OFF + stO)      = bl0;
        *(float4*)(st + BL_OFF + stO + 16) = bl1;
    };

    auto compute = [&](int s) {
        uint32_t stb = sb + s * STAGE_BYTES;
#pragma unroll
        for (int ks = 0; ks < 2; ks++) {
            uint32_t ko = (uint32_t)(ks * 32);
            uint32_t ah[4][4], al[4][4], bh[2][4], bl[2][4];
#pragma unroll
            for (int mt = 0; mt < 4; mt++) {
                ldsm_x4(ah[mt], stb + AH_OFF + lmA + ko + mt * (16 * 80));
                ldsm_x4(al[mt], stb + AL_OFF + lmA + ko + mt * (16 * 80));
            }
#pragma unroll
            for (int nb = 0; nb < 2; nb++) {
                ldsm_x4(bh[nb], stb + BH_OFF + lmB + ko + nb * (16 * 80));
                ldsm_x4(bl[nb], stb + BL_OFF + lmB + ko + nb * (16 * 80));
            }
#pragma unroll
            for (int mt = 0; mt < 4; mt++) {
#pragma unroll
                for (int nb = 0; nb < 2; nb++) {
#pragma unroll
                    for (int nt = 0; nt < 2; nt++) {
                        float* d = acc[mt][nb * 2 + nt];
                        mma_bf16(d, ah[mt], bh[nb][nt], bh[nb][nt + 2]); // hi*hi
                        mma_bf16(d, ah[mt], bl[nb][nt], bl[nb][nt + 2]); // hi*lo
                        mma_bf16(d, al[mt], bh[nb][nt], bh[nb][nt + 2]); // lo*hi
                    }
                }
            }
        }
    };

    const int NT = (NN / 2) / 32;   // 64
    loadG(0);
    storeStage(0);
    __syncthreads();

    for (int t = 0; t < NT; t++) {
        int s = t & 1;
        if (t + 1 < NT) loadG((t + 1) * 32);
        compute(s);
        if (t + 1 < NT) storeStage(s ^ 1);
        __syncthreads();
    }

    // Epilogue: red.v2 split-K partial sums into g_Z1
#pragma unroll
    for (int mt = 0; mt < 4; mt++) {
#pragma unroll
        for (int j = 0; j < 4; j++) {
            int m = row0 + wm * 64 + mt * 16 + (lane >> 2);
            int n = wn * 32 + j * 8 + (lane & 3) * 2;
            float* p0 = &g_Z1[(size_t)m * 128 + n];
            float* p1 = &g_Z1[(size_t)(m + 8) * 128 + n];
            asm volatile("red.global.add.v2.f32 [%0], {%1, %2};"
                         :: "l"(p0), "f"(acc[mt][j][0]), "f"(acc[mt][j][1]) : "memory");
            asm volatile("red.global.add.v2.f32 [%0], {%1, %2};"
                         :: "l"(p1), "f"(acc[mt][j][2]), "f"(acc[mt][j][3]) : "memory");
        }
    }
}

// ---------------------------------------------------------------------------
// Supports layer 1: SUP1[s][n][h] = Wc[s,0]*Z1[n,h] + Wc[s,1]*Z1[n,64+h]
// ---------------------------------------------------------------------------
__global__ __launch_bounds__(256) void sup1_kernel(const float* __restrict__ Wc) {
    int idx = blockIdx.x * blockDim.x + threadIdx.x;  // NN*16 threads
    int n = idx >> 4;
    int g = (idx & 15) << 2;
    float4 z0 = *(const float4*)&g_Z1[(size_t)n * 128 + g];
    float4 z1 = *(const float4*)&g_Z1[(size_t)n * 128 + 64 + g];
#pragma unroll
    for (int s = 0; s < SS; s++) {
        float c0 = Wc[2 * s], c1 = Wc[2 * s + 1];
        float4 o;
        o.x = fmaf(c0, z0.x, c1 * z1.x);
        o.y = fmaf(c0, z0.y, c1 * z1.y);
        o.z = fmaf(c0, z0.z, c1 * z1.z);
        o.w = fmaf(c0, z0.w, c1 * z1.w);
        *(float4*)&g_SUP1[((size_t)s * NN + n) * 64 + g] = o;
    }
}

// ---------------------------------------------------------------------------
// Aggregation layer 1: ACC1[dst] += w_e * SUP1[s][src]   (red.v4)
// ---------------------------------------------------------------------------
__global__ __launch_bounds__(256) void agg1_kernel(const int* __restrict__ src,
                                                   const int* __restrict__ dst,
                                                   const float* __restrict__ w) {
    int idx = blockIdx.x * blockDim.x + threadIdx.x;
    int e = idx >> 4;
    int g = (idx & 15) << 2;
    int s = e >> 18;
    int   sn = src[e];
    int   dn = dst[e];
    float we = w[e];

    float4 z = *(const float4*)&g_SUP1[((size_t)s * NN + sn) * 64 + g];
    float* p = &g_ACC1[(size_t)dn * 64 + g];
    asm volatile("red.global.add.v4.f32 [%0], {%1, %2, %3, %4};"
                 :: "l"(p), "f"(we * z.x), "f"(we * z.y), "f"(we * z.z), "f"(we * z.w)
                 : "memory");
}

// ---------------------------------------------------------------------------
// GEMM2: Z2 = tanh(ACC1) @ W2cat
// ---------------------------------------------------------------------------
__global__ __launch_bounds__(256) void gemm2_kernel(const float* __restrict__ W2) {
    __shared__ float As[64][68];
    __shared__ float Bs[64][64];

    const int tid = threadIdx.x;
    const int tx = tid & 15;
    const int ty = tid >> 4;
    const int row0 = blockIdx.x * 64;

#pragma unroll
    for (int i = 0; i < 4; i++) {
        int idx = tid + i * 256;
        int r = idx >> 4;
        int c = (idx & 15) << 2;
        float4 v = *(const float4*)&g_ACC1[(size_t)(row0 + r) * 64 + c];
        v.x = tanhf(v.x); v.y = tanhf(v.y); v.z = tanhf(v.z); v.w = tanhf(v.w);
        *(float4*)&As[r][c] = v;
    }
#pragma unroll
    for (int i = 0; i < 4; i++) {
        int idx = tid + i * 256;
        int k   = idx >> 4;
        int col = (idx & 15) << 2;
        int b = col >> 5;
        int h = col & 31;
        *(float4*)&Bs[k][col] = *(const float4*)(W2 + (size_t)b * 64 * 32 + (size_t)k * 32 + h);
    }
    __syncthreads();

    float acc[4][4];
#pragma unroll
    for (int i = 0; i < 4; i++)
#pragma unroll
        for (int j = 0; j < 4; j++) acc[i][j] = 0.0f;

#pragma unroll
    for (int k = 0; k < 64; k++) {
        float4 b4 = *(const float4*)&Bs[k][tx << 2];
        float bv[4] = {b4.x, b4.y, b4.z, b4.w};
#pragma unroll
        for (int i = 0; i < 4; i++) {
            float a = As[ty + i * 16][k];
#pragma unroll
            for (int j = 0; j < 4; j++)
                acc[i][j] = fmaf(a, bv[j], acc[i][j]);
        }
    }

#pragma unroll
    for (int i = 0; i < 4; i++) {
        int r = row0 + ty + i * 16;
        float4 o = make_float4(acc[i][0], acc[i][1], acc[i][2], acc[i][3]);
        *(float4*)&g_Z2[(size_t)r * 64 + (tx << 2)] = o;
    }
}

// ---------------------------------------------------------------------------
// Supports layer 2: SUP2[s][n][f] = Wc[s,0]*Z2[n,f] + Wc[s,1]*Z2[n,32+f]
// ---------------------------------------------------------------------------
__global__ __launch_bounds__(256) void sup2_kernel(const float* __restrict__ Wc) {
    int idx = blockIdx.x * blockDim.x + threadIdx.x;  // NN*8 threads
    int n = idx >> 3;
    int g = (idx & 7) << 2;
    float4 z0 = *(const float4*)&g_Z2[(size_t)n * 64 + g];
    float4 z1 = *(const float4*)&g_Z2[(size_t)n * 64 + 32 + g];
#pragma unroll
    for (int s = 0; s < SS; s++) {
        float c0 = Wc[2 * s], c1 = Wc[2 * s + 1];
        float4 o;
        o.x = fmaf(c0, z0.x, c1 * z1.x);
        o.y = fmaf(c0, z0.y, c1 * z1.y);
        o.z = fmaf(c0, z0.z, c1 * z1.z);
        o.w = fmaf(c0, z0.w, c1 * z1.w);
        *(float4*)&g_SUP2[((size_t)s * NN + n) * 32 + g] = o;
    }
}

// ---------------------------------------------------------------------------
// Aggregation layer 2
// ---------------------------------------------------------------------------
__global__ __launch_bounds__(256) void agg2_kernel(const int* __restrict__ src,
                                                   const int* __restrict__ dst,
                                                   const float* __restrict__ w) {
    int idx = blockIdx.x * blockDim.x + threadIdx.x;
    int e = idx >> 3;
    int g = (idx & 7) << 2;
    int s = e >> 18;
    int   sn = src[e];
    int   dn = dst[e];
    float we = w[e];

    float4 z = *(const float4*)&g_SUP2[((size_t)s * NN + sn) * 32 + g];
    float* p = &g_ACC2[(size_t)dn * 32 + g];
    asm volatile("red.global.add.v4.f32 [%0], {%1, %2, %3, %4};"
                 :: "l"(p), "f"(we * z.x), "f"(we * z.y), "f"(we * z.z), "f"(we * z.w)
                 : "memory");
}

// ---------------------------------------------------------------------------
// Classifier
// ---------------------------------------------------------------------------
__global__ void final_kernel(const float* __restrict__ Wclf,
                             const float* __restrict__ bclf,
                             float* __restrict__ out) {
    int n = blockIdx.x * blockDim.x + threadIdx.x;
    if (n >= NN) return;
    float a0 = bclf[0];
    float a1 = bclf[1];
#pragma unroll
    for (int f = 0; f < 32; f++) {
        float v = tanhf(g_ACC2[(size_t)n * 32 + f]);
        a0 = fmaf(v, Wclf[2 * f],     a0);
        a1 = fmaf(v, Wclf[2 * f + 1], a1);
    }
    out[2 * n]     = a0;
    out[2 * n + 1] = a1;
}

// ---------------------------------------------------------------------------
extern "C" void kernel_launch(void* const* d_in, const int* in_sizes, int n_in,
                              void* d_out, int out_size) {
    const float* features = (const float*)d_in[0];
    const float* edge_w   = (const float*)d_in[1];
    const float* W1       = (const float*)d_in[2];
    const float* Wc1      = (const float*)d_in[3];
    const float* W2       = (const float*)d_in[4];
    const float* Wc2      = (const float*)d_in[5];
    const float* Wclf     = (const float*)d_in[6];
    const float* bclf     = (const float*)d_in[7];
    const int*   edge_src = (const int*)d_in[8];
    const int*   edge_dst = (const int*)d_in[9];
    float* out = (float*)d_out;

    cudaFuncSetAttribute(gemm1_mma, cudaFuncAttributeMaxDynamicSharedMemorySize,
                         GEMM1_SMEM);

    zero_kernel<<<(NN * 128 + 255) / 256, 256>>>();
    prep_b_kernel<<<NN / 64, 256>>>(W1);
    gemm1_mma<<<dim3(NN / 128, 2), 256, GEMM1_SMEM>>>(features);
    sup1_kernel<<<NN * 16 / 256, 256>>>(Wc1);
    agg1_kernel<<<SS * EE * 16 / 256, 256>>>(edge_src, edge_dst, edge_w);
    gemm2_kernel<<<NN / 64, 256>>>(W2);
    sup2_kernel<<<NN * 8 / 256, 256>>>(Wc2);
    agg2_kernel<<<SS * EE * 8 / 256, 256>>>(edge_src, edge_dst, edge_w);
    final_kernel<<<(NN + 255) / 256, 256>>>(Wclf, bclf, out);
}